// round 1
// baseline (speedup 1.0000x reference)
#include <cuda_runtime.h>
#include <cuda_bf16.h>
#include <math.h>

// Problem constants
#define B_  8
#define T_  1024
#define D_  512
#define H_  8
#define DK_ 64
#define P_  2047          // 2*T-1
#define NROW_ (B_*T_)     // 8192
#define ND_  (NROW_*D_)   // 4194304

// -------------------- device scratch (no allocs allowed) --------------------
__device__ float g_qn [ND_];
__device__ float g_kn [ND_];
__device__ float g_vn [ND_];
__device__ float g_qu [ND_];   // qh + pos_bias_u   layout [b, t, h, dk]
__device__ float g_qv [ND_];   // qh + pos_bias_v
__device__ float g_kh [ND_];   // layout [b, t, h, dk]
__device__ float g_vh [ND_];
__device__ float g_p  [P_*D_]; // layout [p, h, dk]
__device__ float g_ctx[ND_];   // attn @ V, layout [b, t, h, dk]
__device__ float g_bd [(size_t)B_*H_*T_*P_];  // ~537MB raw bd scores

// ------------------------------ LayerNorm -----------------------------------
__global__ __launch_bounds__(256)
void ln_kernel(const float* __restrict__ x, const float* __restrict__ g,
               const float* __restrict__ bb, float* __restrict__ y)
{
    long row = blockIdx.x;
    const float2* xr = (const float2*)(x + row * D_);
    float2*       yr = (float2*)(y + row * D_);
    int tid = threadIdx.x;             // 256 threads, 2 elems each
    float2 v = xr[tid];
    float s  = v.x + v.y;
    float sq = v.x * v.x + v.y * v.y;

    __shared__ float rs[8], rq[8];
    #pragma unroll
    for (int o = 16; o > 0; o >>= 1) {
        s  += __shfl_xor_sync(0xffffffffu, s,  o);
        sq += __shfl_xor_sync(0xffffffffu, sq, o);
    }
    int wid = tid >> 5;
    if ((tid & 31) == 0) { rs[wid] = s; rq[wid] = sq; }
    __syncthreads();
    if (tid == 0) {
        float a = 0.f, b2 = 0.f;
        #pragma unroll
        for (int w = 0; w < 8; w++) { a += rs[w]; b2 += rq[w]; }
        rs[0] = a; rq[0] = b2;
    }
    __syncthreads();
    float mean = rs[0] * (1.0f / D_);
    float var  = rq[0] * (1.0f / D_) - mean * mean;
    float rstd = rsqrtf(var + 1e-5f);
    const float2* gv2 = (const float2*)g;
    const float2* bv2 = (const float2*)bb;
    float2 gv = gv2[tid], bv = bv2[tid];
    float2 o;
    o.x = (v.x - mean) * rstd * gv.x + bv.x;
    o.y = (v.y - mean) * rstd * gv.y + bv.y;
    yr[tid] = o;
}

// ------------------------------ generic GEMM ---------------------------------
// C[m,n] = alpha * sum_k A[m,k] * (TRANS_B ? Bm[n,k] : Bm[k,n])   (+ residual)
// Two-level batch: z -> (zo = z/batchDiv, zi = z%batchDiv); offsets via strides.
// Dual output: if C2 != null, write C = acc+bias1[n], C2 = acc+bias2[n].
template<int BM, int BN, int BK, int TM, int TN, bool TRANS_B>
__global__ __launch_bounds__((BM/TM)*(BN/TN))
void gemm_kernel(const float* __restrict__ A, const float* __restrict__ Bm,
                 float* __restrict__ C, float* __restrict__ C2,
                 const float* __restrict__ bias1, const float* __restrict__ bias2,
                 const float* __restrict__ Res,
                 int M, int N, int K, int lda, int ldb, int ldc,
                 int batchDiv,
                 long sAo, long sAi, long sBo, long sBi, long sCo, long sCi,
                 float alpha)
{
    constexpr int NT = (BM/TM)*(BN/TN);
    __shared__ float As[BK][BM];
    __shared__ float Bs[BK][BN];

    int z  = blockIdx.z;
    int zo = z / batchDiv, zi = z % batchDiv;
    A  += zo * sAo + zi * sAi;
    Bm += zo * sBo + zi * sBi;
    long coff = zo * sCo + zi * sCi;
    C += coff;
    if (C2)  C2  += coff;
    if (Res) Res += coff;

    int m0 = blockIdx.y * BM, n0 = blockIdx.x * BN;
    int tid = threadIdx.x;
    int ty = tid / (BN/TN), tx = tid % (BN/TN);

    float acc[TM][TN];
    #pragma unroll
    for (int i = 0; i < TM; i++)
        #pragma unroll
        for (int j = 0; j < TN; j++) acc[i][j] = 0.f;

    for (int k0 = 0; k0 < K; k0 += BK) {
        // load A tile (BM x BK), store transposed As[k][m]
        #pragma unroll
        for (int idx = tid; idx < BM*BK; idx += NT) {
            int m = idx / BK, kk = idx % BK;
            int gm = m0 + m;
            As[kk][m] = (gm < M) ? A[(long)gm * lda + (k0 + kk)] : 0.f;
        }
        // load B tile
        if (TRANS_B) {
            #pragma unroll
            for (int idx = tid; idx < BN*BK; idx += NT) {
                int n = idx / BK, kk = idx % BK;
                int gn = n0 + n;
                Bs[kk][n] = (gn < N) ? Bm[(long)gn * ldb + (k0 + kk)] : 0.f;
            }
        } else {
            #pragma unroll
            for (int idx = tid; idx < BN*BK; idx += NT) {
                int kk = idx / BN, n = idx % BN;
                int gn = n0 + n;
                Bs[kk][n] = (gn < N) ? Bm[(long)(k0 + kk) * ldb + gn] : 0.f;
            }
        }
        __syncthreads();

        #pragma unroll
        for (int kk = 0; kk < BK; kk++) {
            float ra[TM], rb[TN];
            #pragma unroll
            for (int i = 0; i < TM; i++) ra[i] = As[kk][ty*TM + i];
            #pragma unroll
            for (int j = 0; j < TN; j++) rb[j] = Bs[kk][tx*TN + j];
            #pragma unroll
            for (int i = 0; i < TM; i++)
                #pragma unroll
                for (int j = 0; j < TN; j++)
                    acc[i][j] += ra[i] * rb[j];
        }
        __syncthreads();
    }

    #pragma unroll
    for (int i = 0; i < TM; i++) {
        int gm = m0 + ty*TM + i;
        if (gm >= M) continue;
        #pragma unroll
        for (int j = 0; j < TN; j++) {
            int gn = n0 + tx*TN + j;
            if (gn >= N) continue;
            float val = acc[i][j] * alpha;
            if (Res) val += Res[(long)gm * ldc + gn];
            if (C2) {
                C [(long)gm * ldc + gn] = val + bias1[gn];
                C2[(long)gm * ldc + gn] = val + bias2[gn];
            } else {
                C[(long)gm * ldc + gn] = val + (bias1 ? bias1[gn] : 0.f);
            }
        }
    }
}

// ------------------- fused rel-shift + mask + softmax ------------------------
// scores[b,h,i,j] = ac[b,h,i,j] (already *scale, in attn buf)
//                 + bd_raw[b,h,i, j + T-1-i] (already *scale)
// mask==0 -> -inf; softmax; masked -> 0; all-masked row -> all zeros.
__global__ __launch_bounds__(256)
void softmax_kernel(float* __restrict__ attn, const float* __restrict__ bd,
                    const int* __restrict__ mask)
{
    int i = blockIdx.x;        // query position
    int z = blockIdx.y;        // b*H + h
    int b = z / H_;
    float*       row = attn + ((long)z * T_ + i) * T_;
    const float* bdr = bd   + ((long)z * T_ + i) * P_ + (T_ - 1 - i);
    const int*   mr  = mask + ((long)b * T_ + i) * T_;

    __shared__ float sbuf[T_];
    __shared__ float red[8];
    int tid = threadIdx.x;
    const float NEG_INF = __int_as_float(0xff800000);

    float lmax = NEG_INF;
    #pragma unroll
    for (int j = tid; j < T_; j += 256) {
        float s = row[j] + bdr[j];
        if (mr[j] == 0) s = NEG_INF;
        sbuf[j] = s;
        lmax = fmaxf(lmax, s);
    }
    #pragma unroll
    for (int o = 16; o > 0; o >>= 1)
        lmax = fmaxf(lmax, __shfl_xor_sync(0xffffffffu, lmax, o));
    if ((tid & 31) == 0) red[tid >> 5] = lmax;
    __syncthreads();
    if (tid == 0) {
        float m = red[0];
        #pragma unroll
        for (int w = 1; w < 8; w++) m = fmaxf(m, red[w]);
        red[0] = m;
    }
    __syncthreads();
    float rowmax = red[0];
    __syncthreads();

    if (rowmax == NEG_INF) {                 // fully masked row -> zeros
        #pragma unroll
        for (int j = tid; j < T_; j += 256) row[j] = 0.f;
        return;
    }

    float lsum = 0.f;
    #pragma unroll
    for (int j = tid; j < T_; j += 256) {
        float e = __expf(sbuf[j] - rowmax);  // exp(-inf)=0 handles masked
        sbuf[j] = e;
        lsum += e;
    }
    #pragma unroll
    for (int o = 16; o > 0; o >>= 1)
        lsum += __shfl_xor_sync(0xffffffffu, lsum, o);
    if ((tid & 31) == 0) red[tid >> 5] = lsum;
    __syncthreads();
    if (tid == 0) {
        float s = 0.f;
        #pragma unroll
        for (int w = 0; w < 8; w++) s += red[w];
        red[0] = s;
    }
    __syncthreads();
    float inv = 1.0f / red[0];
    #pragma unroll
    for (int j = tid; j < T_; j += 256) row[j] = sbuf[j] * inv;
}

// ------------------------------ launch ---------------------------------------
extern "C" void kernel_launch(void* const* d_in, const int* in_sizes, int n_in,
                              void* d_out, int out_size)
{
    const float* q    = (const float*)d_in[0];
    const float* k    = (const float*)d_in[1];
    const float* v    = (const float*)d_in[2];
    const float* pos  = (const float*)d_in[3];
    const int*   mask = (const int*)  d_in[4];
    const float* lnqg = (const float*)d_in[5],  *lnqb = (const float*)d_in[6];
    const float* lnkg = (const float*)d_in[7],  *lnkb = (const float*)d_in[8];
    const float* lnvg = (const float*)d_in[9],  *lnvb = (const float*)d_in[10];
    const float* wq   = (const float*)d_in[11], *wk   = (const float*)d_in[12];
    const float* wv   = (const float*)d_in[13], *wpos = (const float*)d_in[14];
    const float* wfc  = (const float*)d_in[15];
    const float* pbu  = (const float*)d_in[16], *pbv  = (const float*)d_in[17];

    float* out  = (float*)d_out;                 // [B,T,D]
    float* attn = out + (size_t)ND_;             // [B,H,T,T]

    float *qn,*kn,*vn,*qu,*qvb,*kh,*vh,*pb,*bd,*ctx;
    cudaGetSymbolAddress((void**)&qn,  g_qn);
    cudaGetSymbolAddress((void**)&kn,  g_kn);
    cudaGetSymbolAddress((void**)&vn,  g_vn);
    cudaGetSymbolAddress((void**)&qu,  g_qu);
    cudaGetSymbolAddress((void**)&qvb, g_qv);
    cudaGetSymbolAddress((void**)&kh,  g_kh);
    cudaGetSymbolAddress((void**)&vh,  g_vh);
    cudaGetSymbolAddress((void**)&pb,  g_p);
    cudaGetSymbolAddress((void**)&bd,  g_bd);
    cudaGetSymbolAddress((void**)&ctx, g_ctx);

    const float scale = 0.125f;   // 1/sqrt(64)

    // LayerNorms
    ln_kernel<<<NROW_, 256>>>(q, lnqg, lnqb, qn);
    ln_kernel<<<NROW_, 256>>>(k, lnkg, lnkb, kn);
    ln_kernel<<<NROW_, 256>>>(v, lnvg, lnvb, vn);

    // Q projection with dual bias epilogue -> qu = qh+u, qv = qh+v
    gemm_kernel<128,128,8,8,8,true><<<dim3(4,64,1),256>>>(
        qn, wq, qu, qvb, pbu, pbv, nullptr,
        NROW_, D_, D_, D_, D_, D_, 1, 0,0,0,0,0,0, 1.f);
    // K, V projections
    gemm_kernel<128,128,8,8,8,true><<<dim3(4,64,1),256>>>(
        kn, wk, kh, nullptr, nullptr, nullptr, nullptr,
        NROW_, D_, D_, D_, D_, D_, 1, 0,0,0,0,0,0, 1.f);
    gemm_kernel<128,128,8,8,8,true><<<dim3(4,64,1),256>>>(
        vn, wv, vh, nullptr, nullptr, nullptr, nullptr,
        NROW_, D_, D_, D_, D_, D_, 1, 0,0,0,0,0,0, 1.f);
    // pos projection  (M = 2047)
    gemm_kernel<128,128,8,8,8,true><<<dim3(4,16,1),256>>>(
        pos, wpos, pb, nullptr, nullptr, nullptr, nullptr,
        P_, D_, D_, D_, D_, D_, 1, 0,0,0,0,0,0, 1.f);

    // ac = scale * (q+u) @ K^T  -> directly into attn region. batched over (b,h)
    gemm_kernel<128,128,8,8,8,true><<<dim3(8,8,B_*H_),256>>>(
        qu, kh, attn, nullptr, nullptr, nullptr, nullptr,
        T_, T_, DK_, D_, D_, T_, H_,
        (long)T_*D_, DK_, (long)T_*D_, DK_, (long)H_*T_*T_, (long)T_*T_, scale);

    // bd_raw = scale * (q+v) @ P^T   [T x 2047] per (b,h); P shared across b
    gemm_kernel<128,128,8,8,8,true><<<dim3(16,8,B_*H_),256>>>(
        qvb, pb, bd, nullptr, nullptr, nullptr, nullptr,
        T_, P_, DK_, D_, D_, P_, H_,
        (long)T_*D_, DK_, 0L, (long)DK_, (long)H_*T_*P_, (long)T_*P_, scale);

    // fused rel-shift + mask + softmax (in-place in attn region)
    softmax_kernel<<<dim3(T_, B_*H_), 256>>>(attn, bd, mask);

    // ctx = attn @ V   (NN gemm, N = dk = 64)
    gemm_kernel<128,64,8,8,4,false><<<dim3(1,8,B_*H_),256>>>(
        attn, vh, ctx, nullptr, nullptr, nullptr, nullptr,
        T_, DK_, T_, T_, D_, D_, H_,
        (long)H_*T_*T_, (long)T_*T_, (long)T_*D_, DK_, (long)T_*D_, DK_, 1.f);

    // out = ctx @ Wfc^T + residual(q)
    gemm_kernel<128,128,8,8,8,true><<<dim3(4,64,1),256>>>(
        ctx, wfc, out, nullptr, nullptr, nullptr, q,
        NROW_, D_, D_, D_, D_, D_, 1, 0,0,0,0,0,0, 1.f);
}

// round 2
// speedup vs baseline: 1.9229x; 1.9229x over previous
#include <cuda_runtime.h>
#include <cuda_bf16.h>
#include <math.h>
#include <stdint.h>

// Problem constants
#define B_  8
#define T_  1024
#define D_  512
#define H_  8
#define DK_ 64
#define P_  2047          // 2*T-1
#define NROW_ (B_*T_)     // 8192
#define ND_  (NROW_*D_)   // 4194304

// -------------------- device scratch (no allocs allowed) --------------------
__device__ float g_qn [ND_];
__device__ float g_kn [ND_];
__device__ float g_vn [ND_];
__device__ float g_qu [ND_];   // qh + pos_bias_u   layout [b, t, h, dk]
__device__ float g_qv [ND_];   // qh + pos_bias_v
__device__ float g_kh [ND_];   // layout [b, t, h, dk]
__device__ float g_vh [ND_];
__device__ float g_p  [P_*D_]; // layout [p, h, dk]
__device__ float g_ctx[ND_];   // attn @ V, layout [b, t, h, dk]
__device__ float g_bd [(size_t)B_*H_*T_*P_];  // ~537MB raw bd scores

// ------------------------------ LayerNorm -----------------------------------
__global__ __launch_bounds__(256)
void ln_kernel(const float* __restrict__ x, const float* __restrict__ g,
               const float* __restrict__ bb, float* __restrict__ y)
{
    long row = blockIdx.x;
    const float2* xr = (const float2*)(x + row * D_);
    float2*       yr = (float2*)(y + row * D_);
    int tid = threadIdx.x;             // 256 threads, 2 elems each
    float2 v = xr[tid];
    float s  = v.x + v.y;
    float sq = v.x * v.x + v.y * v.y;

    __shared__ float rs[8], rq[8];
    #pragma unroll
    for (int o = 16; o > 0; o >>= 1) {
        s  += __shfl_xor_sync(0xffffffffu, s,  o);
        sq += __shfl_xor_sync(0xffffffffu, sq, o);
    }
    int wid = tid >> 5;
    if ((tid & 31) == 0) { rs[wid] = s; rq[wid] = sq; }
    __syncthreads();
    if (tid == 0) {
        float a = 0.f, b2 = 0.f;
        #pragma unroll
        for (int w = 0; w < 8; w++) { a += rs[w]; b2 += rq[w]; }
        rs[0] = a; rq[0] = b2;
    }
    __syncthreads();
    float mean = rs[0] * (1.0f / D_);
    float var  = rq[0] * (1.0f / D_) - mean * mean;
    float rstd = rsqrtf(var + 1e-5f);
    const float2* gv2 = (const float2*)g;
    const float2* bv2 = (const float2*)bb;
    float2 gv = gv2[tid], bv = bv2[tid];
    float2 o;
    o.x = (v.x - mean) * rstd * gv.x + bv.x;
    o.y = (v.y - mean) * rstd * gv.y + bv.y;
    yr[tid] = o;
}

// ------------------------- TF32 helpers --------------------------------------
__device__ __forceinline__ uint32_t f2tf(float f) {
    uint32_t u;
    asm("cvt.rna.tf32.f32 %0, %1;" : "=r"(u) : "f"(f));
    return u;
}

__device__ __forceinline__ void mma_tf32(float c[4], const uint32_t a[4],
                                         const uint32_t b[2]) {
    asm volatile(
        "mma.sync.aligned.m16n8k8.row.col.f32.tf32.tf32.f32 "
        "{%0,%1,%2,%3},{%4,%5,%6,%7},{%8,%9},{%0,%1,%2,%3};\n"
        : "+f"(c[0]), "+f"(c[1]), "+f"(c[2]), "+f"(c[3])
        : "r"(a[0]), "r"(a[1]), "r"(a[2]), "r"(a[3]), "r"(b[0]), "r"(b[1]));
}

// ------------------------------ TF32 MMA GEMM --------------------------------
// C[m,n] = alpha * sum_k A[m,k] * (TRANS_B ? Bm[n,k] : Bm[k,n])   (+ residual)
// Two-level batch: z -> (zo = z/batchDiv, zi = z%batchDiv); offsets via strides.
// Dual output: if C2 != null, write C = acc+bias1[n], C2 = acc+bias2[n].
// 256 threads, 8 warps; warp tile WM x WN; BK = 16 (2 k-steps of 8).
template<int BM, int BN, int WM, int WN, bool TRANS_B>
__global__ __launch_bounds__(256)
void mma_gemm(const float* __restrict__ A, const float* __restrict__ Bm,
              float* __restrict__ C, float* __restrict__ C2,
              const float* __restrict__ bias1, const float* __restrict__ bias2,
              const float* __restrict__ Res,
              int M, int N, int K, int lda, int ldb, int ldc,
              int batchDiv,
              long sAo, long sAi, long sBo, long sBi, long sCo, long sCi,
              float alpha)
{
    constexpr int BK = 16;
    constexpr int MT = WM / 16;     // m16 tiles per warp
    constexpr int NT = WN / 8;      // n8 tiles per warp
    constexpr int WCOLS = BN / WN;  // warps along n
    static_assert((BM / WM) * (BN / WN) == 8, "8 warps required");

    __shared__ uint32_t As[BK][BM + 4];
    __shared__ uint32_t Bs[BK][BN + 4];

    int z  = blockIdx.z;
    int zo = z / batchDiv, zi = z % batchDiv;
    A  += zo * sAo + zi * sAi;
    Bm += zo * sBo + zi * sBi;
    long coff = zo * sCo + zi * sCi;
    C += coff;
    if (C2)  C2  += coff;
    if (Res) Res += coff;

    int m0 = blockIdx.y * BM, n0 = blockIdx.x * BN;
    int tid  = threadIdx.x;
    int warp = tid >> 5, lane = tid & 31;
    int wm0 = (warp / WCOLS) * WM;
    int wn0 = (warp % WCOLS) * WN;

    float acc[MT][NT][4];
    #pragma unroll
    for (int i = 0; i < MT; i++)
        #pragma unroll
        for (int j = 0; j < NT; j++)
            #pragma unroll
            for (int e = 0; e < 4; e++) acc[i][j][e] = 0.f;

    for (int k0 = 0; k0 < K; k0 += BK) {
        // ---- load A tile (BM x 16 floats), transposed into As[k][m] ----
        #pragma unroll
        for (int s = tid; s < BM * (BK / 4); s += 256) {
            int row = s >> 2;          // m within tile
            int kq  = s & 3;           // which float4 of the 16-wide k chunk
            int gm  = m0 + row;
            float4 v = make_float4(0.f, 0.f, 0.f, 0.f);
            if (gm < M)
                v = *(const float4*)(A + (long)gm * lda + k0 + kq * 4);
            As[kq * 4 + 0][row] = f2tf(v.x);
            As[kq * 4 + 1][row] = f2tf(v.y);
            As[kq * 4 + 2][row] = f2tf(v.z);
            As[kq * 4 + 3][row] = f2tf(v.w);
        }
        // ---- load B tile into Bs[k][n] ----
        if (TRANS_B) {
            #pragma unroll
            for (int s = tid; s < BN * (BK / 4); s += 256) {
                int n  = s >> 2;
                int kq = s & 3;
                int gn = n0 + n;
                float4 v = make_float4(0.f, 0.f, 0.f, 0.f);
                if (gn < N)
                    v = *(const float4*)(Bm + (long)gn * ldb + k0 + kq * 4);
                Bs[kq * 4 + 0][n] = f2tf(v.x);
                Bs[kq * 4 + 1][n] = f2tf(v.y);
                Bs[kq * 4 + 2][n] = f2tf(v.z);
                Bs[kq * 4 + 3][n] = f2tf(v.w);
            }
        } else {
            #pragma unroll
            for (int s = tid; s < BK * (BN / 4); s += 256) {
                int kk = s / (BN / 4);
                int nq = s % (BN / 4);
                float4 v = *(const float4*)(Bm + (long)(k0 + kk) * ldb + n0 + nq * 4);
                Bs[kk][nq * 4 + 0] = f2tf(v.x);
                Bs[kk][nq * 4 + 1] = f2tf(v.y);
                Bs[kk][nq * 4 + 2] = f2tf(v.z);
                Bs[kk][nq * 4 + 3] = f2tf(v.w);
            }
        }
        __syncthreads();

        // ---- 2 k-steps of 8 ----
        #pragma unroll
        for (int ks = 0; ks < 2; ks++) {
            const int kb = ks * 8;
            uint32_t af[MT][4];
            uint32_t bf[NT][2];
            #pragma unroll
            for (int mt = 0; mt < MT; mt++) {
                int mrow = wm0 + mt * 16 + (lane >> 2);
                af[mt][0] = As[kb + (lane & 3)][mrow];
                af[mt][1] = As[kb + (lane & 3)][mrow + 8];
                af[mt][2] = As[kb + 4 + (lane & 3)][mrow];
                af[mt][3] = As[kb + 4 + (lane & 3)][mrow + 8];
            }
            #pragma unroll
            for (int nt = 0; nt < NT; nt++) {
                int ncol = wn0 + nt * 8 + (lane >> 2);
                bf[nt][0] = Bs[kb + (lane & 3)][ncol];
                bf[nt][1] = Bs[kb + 4 + (lane & 3)][ncol];
            }
            #pragma unroll
            for (int mt = 0; mt < MT; mt++)
                #pragma unroll
                for (int nt = 0; nt < NT; nt++)
                    mma_tf32(acc[mt][nt], af[mt], bf[nt]);
        }
        __syncthreads();
    }

    // ---- epilogue ----
    auto emit = [&](int gm, int gn, float v) {
        if (gm < M && gn < N) {
            float val = v * alpha;
            if (Res) val += Res[(long)gm * ldc + gn];
            if (C2) {
                C [(long)gm * ldc + gn] = val + bias1[gn];
                C2[(long)gm * ldc + gn] = val + bias2[gn];
            } else {
                C[(long)gm * ldc + gn] = val + (bias1 ? bias1[gn] : 0.f);
            }
        }
    };
    #pragma unroll
    for (int mt = 0; mt < MT; mt++) {
        #pragma unroll
        for (int nt = 0; nt < NT; nt++) {
            int gm = m0 + wm0 + mt * 16 + (lane >> 2);
            int gn = n0 + wn0 + nt * 8 + 2 * (lane & 3);
            emit(gm,     gn,     acc[mt][nt][0]);
            emit(gm,     gn + 1, acc[mt][nt][1]);
            emit(gm + 8, gn,     acc[mt][nt][2]);
            emit(gm + 8, gn + 1, acc[mt][nt][3]);
        }
    }
}

// ------------------- fused rel-shift + mask + softmax ------------------------
__global__ __launch_bounds__(256)
void softmax_kernel(float* __restrict__ attn, const float* __restrict__ bd,
                    const int* __restrict__ mask)
{
    int i = blockIdx.x;        // query position
    int z = blockIdx.y;        // b*H + h
    int b = z / H_;
    float*       row = attn + ((long)z * T_ + i) * T_;
    const float* bdr = bd   + ((long)z * T_ + i) * P_ + (T_ - 1 - i);
    const int*   mr  = mask + ((long)b * T_ + i) * T_;

    __shared__ float sbuf[T_];
    __shared__ float red[8];
    int tid = threadIdx.x;
    const float NEG_INF = __int_as_float(0xff800000);

    float lmax = NEG_INF;
    #pragma unroll
    for (int j = tid; j < T_; j += 256) {
        float s = row[j] + bdr[j];
        if (mr[j] == 0) s = NEG_INF;
        sbuf[j] = s;
        lmax = fmaxf(lmax, s);
    }
    #pragma unroll
    for (int o = 16; o > 0; o >>= 1)
        lmax = fmaxf(lmax, __shfl_xor_sync(0xffffffffu, lmax, o));
    if ((tid & 31) == 0) red[tid >> 5] = lmax;
    __syncthreads();
    if (tid == 0) {
        float m = red[0];
        #pragma unroll
        for (int w = 1; w < 8; w++) m = fmaxf(m, red[w]);
        red[0] = m;
    }
    __syncthreads();
    float rowmax = red[0];
    __syncthreads();

    if (rowmax == NEG_INF) {
        #pragma unroll
        for (int j = tid; j < T_; j += 256) row[j] = 0.f;
        return;
    }

    float lsum = 0.f;
    #pragma unroll
    for (int j = tid; j < T_; j += 256) {
        float e = __expf(sbuf[j] - rowmax);
        sbuf[j] = e;
        lsum += e;
    }
    #pragma unroll
    for (int o = 16; o > 0; o >>= 1)
        lsum += __shfl_xor_sync(0xffffffffu, lsum, o);
    if ((tid & 31) == 0) red[tid >> 5] = lsum;
    __syncthreads();
    if (tid == 0) {
        float s = 0.f;
        #pragma unroll
        for (int w = 0; w < 8; w++) s += red[w];
        red[0] = s;
    }
    __syncthreads();
    float inv = 1.0f / red[0];
    #pragma unroll
    for (int j = tid; j < T_; j += 256) row[j] = sbuf[j] * inv;
}

// ------------------------------ launch ---------------------------------------
extern "C" void kernel_launch(void* const* d_in, const int* in_sizes, int n_in,
                              void* d_out, int out_size)
{
    const float* q    = (const float*)d_in[0];
    const float* k    = (const float*)d_in[1];
    const float* v    = (const float*)d_in[2];
    const float* pos  = (const float*)d_in[3];
    const int*   mask = (const int*)  d_in[4];
    const float* lnqg = (const float*)d_in[5],  *lnqb = (const float*)d_in[6];
    const float* lnkg = (const float*)d_in[7],  *lnkb = (const float*)d_in[8];
    const float* lnvg = (const float*)d_in[9],  *lnvb = (const float*)d_in[10];
    const float* wq   = (const float*)d_in[11], *wk   = (const float*)d_in[12];
    const float* wv   = (const float*)d_in[13], *wpos = (const float*)d_in[14];
    const float* wfc  = (const float*)d_in[15];
    const float* pbu  = (const float*)d_in[16], *pbv  = (const float*)d_in[17];

    float* out  = (float*)d_out;                 // [B,T,D]
    float* attn = out + (size_t)ND_;             // [B,H,T,T]

    float *qn,*kn,*vn,*qu,*qvb,*kh,*vh,*pb,*bd,*ctx;
    cudaGetSymbolAddress((void**)&qn,  g_qn);
    cudaGetSymbolAddress((void**)&kn,  g_kn);
    cudaGetSymbolAddress((void**)&vn,  g_vn);
    cudaGetSymbolAddress((void**)&qu,  g_qu);
    cudaGetSymbolAddress((void**)&qvb, g_qv);
    cudaGetSymbolAddress((void**)&kh,  g_kh);
    cudaGetSymbolAddress((void**)&vh,  g_vh);
    cudaGetSymbolAddress((void**)&pb,  g_p);
    cudaGetSymbolAddress((void**)&bd,  g_bd);
    cudaGetSymbolAddress((void**)&ctx, g_ctx);

    const float scale = 0.125f;   // 1/sqrt(64)

    // LayerNorms
    ln_kernel<<<NROW_, 256>>>(q, lnqg, lnqb, qn);
    ln_kernel<<<NROW_, 256>>>(k, lnkg, lnkb, kn);
    ln_kernel<<<NROW_, 256>>>(v, lnvg, lnvb, vn);

    // Q projection with dual bias epilogue -> qu = qh+u, qv = qh+v
    mma_gemm<128,128,64,32,true><<<dim3(4,64,1),256>>>(
        qn, wq, qu, qvb, pbu, pbv, nullptr,
        NROW_, D_, D_, D_, D_, D_, 1, 0,0,0,0,0,0, 1.f);
    // K, V projections
    mma_gemm<128,128,64,32,true><<<dim3(4,64,1),256>>>(
        kn, wk, kh, nullptr, nullptr, nullptr, nullptr,
        NROW_, D_, D_, D_, D_, D_, 1, 0,0,0,0,0,0, 1.f);
    mma_gemm<128,128,64,32,true><<<dim3(4,64,1),256>>>(
        vn, wv, vh, nullptr, nullptr, nullptr, nullptr,
        NROW_, D_, D_, D_, D_, D_, 1, 0,0,0,0,0,0, 1.f);
    // pos projection  (M = 2047)
    mma_gemm<128,128,64,32,true><<<dim3(4,16,1),256>>>(
        pos, wpos, pb, nullptr, nullptr, nullptr, nullptr,
        P_, D_, D_, D_, D_, D_, 1, 0,0,0,0,0,0, 1.f);

    // ac = scale * (q+u) @ K^T  -> directly into attn region. batched over (b,h)
    mma_gemm<128,128,64,32,true><<<dim3(8,8,B_*H_),256>>>(
        qu, kh, attn, nullptr, nullptr, nullptr, nullptr,
        T_, T_, DK_, D_, D_, T_, H_,
        (long)T_*D_, DK_, (long)T_*D_, DK_, (long)H_*T_*T_, (long)T_*T_, scale);

    // bd_raw = scale * (q+v) @ P^T   [T x 2047] per (b,h); P shared across b
    mma_gemm<128,128,64,32,true><<<dim3(16,8,B_*H_),256>>>(
        qvb, pb, bd, nullptr, nullptr, nullptr, nullptr,
        T_, P_, DK_, D_, D_, P_, H_,
        (long)T_*D_, DK_, 0L, (long)DK_, (long)H_*T_*P_, (long)T_*P_, scale);

    // fused rel-shift + mask + softmax (in-place in attn region)
    softmax_kernel<<<dim3(T_, B_*H_), 256>>>(attn, bd, mask);

    // ctx = attn @ V   (NN gemm, N = dk = 64)
    mma_gemm<128,64,64,16,false><<<dim3(1,8,B_*H_),256>>>(
        attn, vh, ctx, nullptr, nullptr, nullptr, nullptr,
        T_, DK_, T_, T_, D_, D_, H_,
        (long)H_*T_*T_, (long)T_*T_, (long)T_*D_, DK_, (long)T_*D_, DK_, 1.f);

    // out = ctx @ Wfc^T + residual(q)
    mma_gemm<128,128,64,32,true><<<dim3(4,64,1),256>>>(
        ctx, wfc, out, nullptr, nullptr, nullptr, q,
        NROW_, D_, D_, D_, D_, D_, 1, 0,0,0,0,0,0, 1.f);
}